// round 15
// baseline (speedup 1.0000x reference)
#include <cuda_runtime.h>
#include <cuda_fp16.h>
#include <cuda_bf16.h>
#include <cstdint>

#define N_NODES 100000
#define N_EDGES 1600000
#define K_DIM   256
#define HD      128     // HEADS * OUT_DIM
#define HEADS   4
#define ODIM    32
#define NEG_SLOPE 0.2f

#define BPAD    136     // padded row stride in bf16 elems (272 B; 17x16B -> conflict-free)
#define NB_SCAN 98      // ceil(100000/1024)

// ---------------- scratch (static device globals; no runtime allocation) ----
__device__ __half g_feat_h[(size_t)N_NODES * HD];   // 25.6 MB
__device__ float  g_el[N_NODES * HEADS];
__device__ float  g_er[N_NODES * HEADS];
__device__ float  g_e[(size_t)N_EDGES * HEADS];     // ex, dst-sorted by position
__device__ int    g_srcp[N_EDGES];                  // src, dst-sorted by position
__device__ float  g_denom[N_NODES * HEADS];
__device__ int    g_cnt[N_NODES];                   // in-degree histogram
__device__ int    g_start[N_NODES + 1];             // CSR row starts
__device__ int    g_cursor[N_NODES];                // permute cursors
__device__ int    g_bsum[128];                      // scan block sums
__device__ __align__(16) __nv_bfloat16 g_Bhi[K_DIM * BPAD];  // W hi, padded [k][n]
__device__ __align__(16) __nv_bfloat16 g_Blo[K_DIM * BPAD];  // W lo

// ---------------- helpers ---------------------------------------------------
__device__ __forceinline__ uint32_t smem_u32(const void* p) {
    uint32_t a;
    asm("{ .reg .u64 t; cvta.to.shared.u64 t, %1; cvt.u32.u64 %0, t; }"
        : "=r"(a) : "l"(p));
    return a;
}
__device__ __forceinline__ void ldsm4(uint32_t* r, uint32_t a) {
    asm volatile("ldmatrix.sync.aligned.m8n8.x4.shared.b16 {%0,%1,%2,%3}, [%4];"
                 : "=r"(r[0]), "=r"(r[1]), "=r"(r[2]), "=r"(r[3]) : "r"(a));
}
__device__ __forceinline__ void ldsm4t(uint32_t* r, uint32_t a) {
    asm volatile("ldmatrix.sync.aligned.m8n8.x4.trans.shared.b16 {%0,%1,%2,%3}, [%4];"
                 : "=r"(r[0]), "=r"(r[1]), "=r"(r[2]), "=r"(r[3]) : "r"(a));
}
__device__ __forceinline__ void mma_bf16(float* c, const uint32_t* a,
                                         uint32_t b0, uint32_t b1) {
    asm volatile(
        "mma.sync.aligned.m16n8k16.row.col.f32.bf16.bf16.f32 "
        "{%0,%1,%2,%3}, {%4,%5,%6,%7}, {%8,%9}, {%0,%1,%2,%3};"
        : "+f"(c[0]), "+f"(c[1]), "+f"(c[2]), "+f"(c[3])
        : "r"(a[0]), "r"(a[1]), "r"(a[2]), "r"(a[3]), "r"(b0), "r"(b1));
}
__device__ __forceinline__ float lrelu(float v) { return v > 0.f ? v : NEG_SLOPE * v; }

// ---------------- SMEM layout (bytes) ---------------------------------------
#define AS_HI   0
#define AS_LO   34816
#define BS_HI   69632
#define BS_LO   139264
#define SM_ATTNL 208896
#define SM_ATTNR 209408
#define SM_TOTAL 209920

// ---------------- sort pipeline ---------------------------------------------

// zero denom + histogram (out no longer needs zeroing: agg_sorted writes all)
__global__ void init_kernel() {
    int i = blockIdx.x * blockDim.x + threadIdx.x;
    if (i < N_NODES * HEADS) g_denom[i] = 0.f;
    if (i < N_NODES) g_cnt[i] = 0;
}

__global__ void hist_kernel(const int* __restrict__ dst) {
    int e = blockIdx.x * blockDim.x + threadIdx.x;
    if (e < N_EDGES) atomicAdd(&g_cnt[dst[e]], 1);
}

// per-block exclusive scan (1024 elems) + block sums
__global__ void scan1_kernel() {
    __shared__ int sm[1024];
    int tid = threadIdx.x;
    int i = blockIdx.x * 1024 + tid;
    int v = (i < N_NODES) ? g_cnt[i] : 0;
    sm[tid] = v;
    __syncthreads();
    #pragma unroll
    for (int off = 1; off < 1024; off <<= 1) {
        int add = (tid >= off) ? sm[tid - off] : 0;
        __syncthreads();
        sm[tid] += add;
        __syncthreads();
    }
    if (i < N_NODES) g_start[i] = sm[tid] - v;     // exclusive
    if (tid == 1023) g_bsum[blockIdx.x] = sm[1023];
}

// serial exclusive scan of the 98 block sums (trivial size)
__global__ void scan2_kernel() {
    if (threadIdx.x == 0 && blockIdx.x == 0) {
        int run = 0;
        for (int b = 0; b < NB_SCAN; b++) { int v = g_bsum[b]; g_bsum[b] = run; run += v; }
    }
}

// add block offsets; clone into cursors; sentinel
__global__ void scan3_kernel() {
    int i = blockIdx.x * blockDim.x + threadIdx.x;
    if (i < N_NODES) {
        int s = g_start[i] + g_bsum[i >> 10];
        g_start[i]  = s;
        g_cursor[i] = s;
    }
    if (i == 0) g_start[N_NODES] = N_EDGES;
}

// ---------------- GEMM (unchanged from passing R13) --------------------------

__global__ void prep_W(const float* __restrict__ W) {
    int idx = blockIdx.x * blockDim.x + threadIdx.x;   // k*128 + n
    if (idx >= K_DIM * HD) return;
    int k = idx >> 7, n = idx & 127;
    float v = W[idx];
    __nv_bfloat16 hi = __float2bfloat16(v);
    __nv_bfloat16 lo = __float2bfloat16(v - __bfloat162float(hi));
    g_Bhi[k * BPAD + n] = hi;
    g_Blo[k * BPAD + n] = lo;
}

__global__ void __launch_bounds__(256, 1)
gemm_mma(const float* __restrict__ x,
         const float* __restrict__ attn_l, const float* __restrict__ attn_r) {
    extern __shared__ char smem[];
    const uint32_t sb = smem_u32(smem);
    const int tid  = threadIdx.x;
    const int wid  = tid >> 5;
    const int lane = tid & 31;
    const int wm   = wid >> 1;
    const int wn   = wid & 1;
    const int lr   = lane & 15;
    const int lc   = lane >> 4;
    const int brow = blockIdx.x * 128;

    if (tid < 128) {
        ((float*)(smem + SM_ATTNL))[tid] = attn_l[tid];
        ((float*)(smem + SM_ATTNR))[tid] = attn_r[tid];
    }
    {
        const uint4* bh = (const uint4*)g_Bhi;
        const uint4* bl = (const uint4*)g_Blo;
        uint4* dh = (uint4*)(smem + BS_HI);
        uint4* dl = (uint4*)(smem + BS_LO);
        #pragma unroll
        for (int i = 0; i < 17; i++) {
            dh[i * 256 + tid] = bh[i * 256 + tid];
            dl[i * 256 + tid] = bl[i * 256 + tid];
        }
    }

    float acc[2][8][4];
    #pragma unroll
    for (int f = 0; f < 2; f++)
        #pragma unroll
        for (int t = 0; t < 8; t++)
            #pragma unroll
            for (int i = 0; i < 4; i++) acc[f][t][i] = 0.f;

    const float4* x4 = (const float4*)x;

    #pragma unroll
    for (int phase = 0; phase < 2; phase++) {
        #pragma unroll
        for (int i = 0; i < 8; i++) {
            int cid = i * 256 + tid;
            int row = cid >> 4;
            int kc  = cid & 15;
            int gr  = brow + row;
            float4 v0 = make_float4(0.f, 0.f, 0.f, 0.f), v1 = v0;
            if (gr < N_NODES) {
                v0 = x4[(size_t)gr * 64 + phase * 32 + kc * 2];
                v1 = x4[(size_t)gr * 64 + phase * 32 + kc * 2 + 1];
            }
            float f[8] = {v0.x, v0.y, v0.z, v0.w, v1.x, v1.y, v1.z, v1.w};
            __align__(16) __nv_bfloat16 hi8[8], lo8[8];
            #pragma unroll
            for (int j = 0; j < 8; j++) {
                hi8[j] = __float2bfloat16(f[j]);
                lo8[j] = __float2bfloat16(f[j] - __bfloat162float(hi8[j]));
            }
            *(uint4*)(smem + AS_HI + row * (BPAD * 2) + kc * 16) = *(const uint4*)hi8;
            *(uint4*)(smem + AS_LO + row * (BPAD * 2) + kc * 16) = *(const uint4*)lo8;
        }
        __syncthreads();

        #pragma unroll
        for (int step = 0; step < 8; step++) {
            const int k0 = step * 16;
            uint32_t ah[2][4], al[2][4];
            uint32_t aBase = sb + (uint32_t)((wm * 32 + lr) * (BPAD * 2) + lc * 16 + k0 * 2);
            ldsm4(ah[0], aBase + AS_HI);
            ldsm4(ah[1], aBase + AS_HI + 16 * (BPAD * 2));
            ldsm4(al[0], aBase + AS_LO);
            ldsm4(al[1], aBase + AS_LO + 16 * (BPAD * 2));
            #pragma unroll
            for (int j = 0; j < 4; j++) {
                uint32_t bAddr = sb + BS_HI +
                    (uint32_t)((phase * 128 + k0 + lr) * (BPAD * 2) +
                               (wn * 64 + j * 16 + lc * 8) * 2);
                uint32_t bh[4], bl[4];
                ldsm4t(bh, bAddr);
                ldsm4t(bl, bAddr + (BS_LO - BS_HI));
                #pragma unroll
                for (int f = 0; f < 2; f++) {
                    mma_bf16(acc[f][2 * j],     ah[f], bh[0], bh[1]);
                    mma_bf16(acc[f][2 * j],     al[f], bh[0], bh[1]);
                    mma_bf16(acc[f][2 * j],     ah[f], bl[0], bl[1]);
                    mma_bf16(acc[f][2 * j + 1], ah[f], bh[2], bh[3]);
                    mma_bf16(acc[f][2 * j + 1], al[f], bh[2], bh[3]);
                    mma_bf16(acc[f][2 * j + 1], ah[f], bl[2], bl[3]);
                }
            }
        }
        __syncthreads();
    }

    #pragma unroll
    for (int f = 0; f < 2; f++) {
        #pragma unroll
        for (int t = 0; t < 8; t++) {
            int row0 = wm * 32 + f * 16 + (lane >> 2);
            int colB = (wn * 64 + t * 8 + (lane & 3) * 2) * 2;
            *(__half2*)(smem + row0 * (BPAD * 2) + colB) =
                __floats2half2_rn(acc[f][t][0], acc[f][t][1]);
            *(__half2*)(smem + (row0 + 8) * (BPAD * 2) + colB) =
                __floats2half2_rn(acc[f][t][2], acc[f][t][3]);
        }
    }
    __syncthreads();

    #pragma unroll
    for (int i = 0; i < 8; i++) {
        int q   = i * 256 + tid;
        int row = q >> 4;
        int cq  = q & 15;
        int gr  = brow + row;
        if (gr < N_NODES)
            ((uint4*)g_feat_h)[(size_t)gr * 16 + cq] =
                *(const uint4*)(smem + row * (BPAD * 2) + cq * 16);
    }

    if (tid < 128) {
        int gr = brow + tid;
        if (gr < N_NODES) {
            const float* sl = (const float*)(smem + SM_ATTNL);
            const float* sr = (const float*)(smem + SM_ATTNR);
            float el[4] = {0.f, 0.f, 0.f, 0.f}, er[4] = {0.f, 0.f, 0.f, 0.f};
            #pragma unroll
            for (int c16 = 0; c16 < 16; c16++) {
                uint4 raw = *(const uint4*)(smem + tid * (BPAD * 2) + c16 * 16);
                const __half2* hp = (const __half2*)&raw;
                int h = c16 >> 2;
                #pragma unroll
                for (int j = 0; j < 4; j++) {
                    float2 fv = __half22float2(hp[j]);
                    int col = c16 * 8 + j * 2;
                    el[h] += fv.x * sl[col] + fv.y * sl[col + 1];
                    er[h] += fv.x * sr[col] + fv.y * sr[col + 1];
                }
            }
            #pragma unroll
            for (int h = 0; h < 4; h++) {
                g_el[gr * 4 + h] = el[h];
                g_er[gr * 4 + h] = er[h];
            }
        }
    }
}

// ---------------- edge pass: softmax numerator + denom + dst-sort scatter ----
// ex = exp(lrelu(el[src]+er[dst])) (shift-free softmax: logits bounded);
// denom[dst] += ex; claim sorted slot via cursor; scatter ex + src there.
__global__ void edge_perm_kernel(const int* __restrict__ src,
                                 const int* __restrict__ dst) {
    int e = blockIdx.x * blockDim.x + threadIdx.x;
    if (e >= N_EDGES) return;
    int s = src[e], d = dst[e];
    float4 l = __ldg((const float4*)g_el + s);
    float4 r = __ldg((const float4*)g_er + d);
    float4 ex;
    ex.x = __expf(lrelu(l.x + r.x));
    ex.y = __expf(lrelu(l.y + r.y));
    ex.z = __expf(lrelu(l.z + r.z));
    ex.w = __expf(lrelu(l.w + r.w));
    atomicAdd((float4*)(g_denom + d * 4), ex);
    int pos = atomicAdd(&g_cursor[d], 1);
    ((float4*)g_e)[pos] = ex;
    g_srcp[pos] = s;
}

// ---------------- atomic-free segment aggregation ---------------------------
// 4 threads per dst node; thread t owns out dims t*8..t*8+7.
// Walks the dst's contiguous edge segment; registers accumulate; plain stores.
__global__ void agg_sorted_kernel(float* __restrict__ out) {
    unsigned gt = blockIdx.x * blockDim.x + threadIdx.x;
    int g = gt >> 2;
    int t = gt & 3;
    if (g >= N_NODES) return;
    int beg = __ldg(&g_start[g]);
    int end = __ldg(&g_start[g + 1]);

    float4 dn = *(const float4*)(g_denom + g * 4);
    float4 inv;
    inv.x = 0.25f / fmaxf(dn.x, 1e-9f);
    inv.y = 0.25f / fmaxf(dn.y, 1e-9f);
    inv.z = 0.25f / fmaxf(dn.z, 1e-9f);
    inv.w = 0.25f / fmaxf(dn.w, 1e-9f);

    float acc[8] = {0.f, 0.f, 0.f, 0.f, 0.f, 0.f, 0.f, 0.f};
    for (int i = beg; i < end; i++) {
        int s = __ldg(g_srcp + i);
        float4 ex = __ldg((const float4*)g_e + i);
        float a[4] = {ex.x * inv.x, ex.y * inv.y, ex.z * inv.z, ex.w * inv.w};
        const uint4* fh = (const uint4*)g_feat_h + (size_t)s * 16 + t;
        #pragma unroll
        for (int h = 0; h < 4; h++) {
            uint4 raw = __ldg(fh + h * 4);
            const __half2* hp = (const __half2*)&raw;
            #pragma unroll
            for (int j = 0; j < 4; j++) {
                float2 f = __half22float2(hp[j]);
                acc[2 * j]     += a[h] * f.x;
                acc[2 * j + 1] += a[h] * f.y;
            }
        }
    }
    float4* op = (float4*)out + (size_t)g * 8 + t * 2;
    op[0] = make_float4(acc[0], acc[1], acc[2], acc[3]);
    op[1] = make_float4(acc[4], acc[5], acc[6], acc[7]);
}

// ---------------- launch ----------------------------------------------------
extern "C" void kernel_launch(void* const* d_in, const int* in_sizes, int n_in,
                              void* d_out, int out_size) {
    const float* x      = (const float*)d_in[0];
    const float* W      = (const float*)d_in[1];
    const float* attn_l = (const float*)d_in[2];
    const float* attn_r = (const float*)d_in[3];
    const int*   src    = (const int*)d_in[4];
    const int*   dst    = (const int*)d_in[5];
    float* out = (float*)d_out;

    cudaFuncSetAttribute(gemm_mma,
                         cudaFuncAttributeMaxDynamicSharedMemorySize, SM_TOTAL);

    init_kernel<<<(N_NODES * HEADS + 255) / 256, 256>>>();
    hist_kernel<<<(N_EDGES + 255) / 256, 256>>>(dst);
    scan1_kernel<<<NB_SCAN, 1024>>>();
    scan2_kernel<<<1, 32>>>();
    scan3_kernel<<<(N_NODES + 255) / 256, 256>>>();
    prep_W<<<(K_DIM * HD + 255) / 256, 256>>>(W);
    gemm_mma<<<(N_NODES + 127) / 128, 256, SM_TOTAL>>>(x, attn_l, attn_r);
    edge_perm_kernel<<<(N_EDGES + 255) / 256, 256>>>(src, dst);
    agg_sorted_kernel<<<(N_NODES * 4 + 255) / 256, 256>>>(out);
}

// round 16
// speedup vs baseline: 1.2087x; 1.2087x over previous
#include <cuda_runtime.h>
#include <cuda_fp16.h>
#include <cstdint>

#define N_NODES 100000
#define N_EDGES 1600000
#define K_DIM   256
#define HD      128     // HEADS * OUT_DIM
#define HEADS   4
#define ODIM    32
#define NEG_SLOPE 0.2f

#define BPAD    136     // padded row stride in fp16 elems (272 B; 17x16B -> conflict-free)

// ---------------- scratch (static device globals; no runtime allocation) ----
__device__ __half g_feat_h[(size_t)N_NODES * HD];   // 25.6 MB
__device__ float  g_el[N_NODES * HEADS];
__device__ float  g_er[N_NODES * HEADS];
__device__ float  g_e[(size_t)N_EDGES * HEADS];     // exp(lrelu(logit))
__device__ float  g_denom[N_NODES * HEADS];
__device__ float  g_inv[N_NODES * HEADS];
__device__ __align__(16) __half g_Bhi[K_DIM * BPAD];  // W hi fp16, padded [k][n]
__device__ __align__(16) __half g_Blo[K_DIM * BPAD];  // W lo fp16

// ---------------- helpers ---------------------------------------------------
__device__ __forceinline__ uint32_t smem_u32(const void* p) {
    uint32_t a;
    asm("{ .reg .u64 t; cvta.to.shared.u64 t, %1; cvt.u32.u64 %0, t; }"
        : "=r"(a) : "l"(p));
    return a;
}
__device__ __forceinline__ void ldsm4(uint32_t* r, uint32_t a) {
    asm volatile("ldmatrix.sync.aligned.m8n8.x4.shared.b16 {%0,%1,%2,%3}, [%4];"
                 : "=r"(r[0]), "=r"(r[1]), "=r"(r[2]), "=r"(r[3]) : "r"(a));
}
__device__ __forceinline__ void ldsm4t(uint32_t* r, uint32_t a) {
    asm volatile("ldmatrix.sync.aligned.m8n8.x4.trans.shared.b16 {%0,%1,%2,%3}, [%4];"
                 : "=r"(r[0]), "=r"(r[1]), "=r"(r[2]), "=r"(r[3]) : "r"(a));
}
__device__ __forceinline__ void mma_f16(float* c, const uint32_t* a,
                                        uint32_t b0, uint32_t b1) {
    asm volatile(
        "mma.sync.aligned.m16n8k16.row.col.f32.f16.f16.f32 "
        "{%0,%1,%2,%3}, {%4,%5,%6,%7}, {%8,%9}, {%0,%1,%2,%3};"
        : "+f"(c[0]), "+f"(c[1]), "+f"(c[2]), "+f"(c[3])
        : "r"(a[0]), "r"(a[1]), "r"(a[2]), "r"(a[3]), "r"(b0), "r"(b1));
}
__device__ __forceinline__ float lrelu(float v) { return v > 0.f ? v : NEG_SLOPE * v; }

// ---------------- SMEM layout (bytes) ---------------------------------------
#define AS_OFF   0                      // A fp16: 128 x BPAD = 34816 (feat tile reuse)
#define BS_HI    34816                  // B hi: 256 x BPAD fp16 = 69632
#define BS_LO    104448                 // B lo: 69632
#define SM_ATTNL 174080
#define SM_ATTNR 174592
#define SM_TOTAL 175104

// ---------------- kernels ---------------------------------------------------

__global__ void init_kernel(float* __restrict__ out) {
    int i = blockIdx.x * blockDim.x + threadIdx.x;
    if (i < N_NODES * ODIM) out[i] = 0.f;
    if (i < N_NODES * HEADS) g_denom[i] = 0.f;
}

// split W[k][n] fp32 -> fp16 hi/lo into padded [k][BPAD] gmem arrays
__global__ void prep_W(const float* __restrict__ W) {
    int idx = blockIdx.x * blockDim.x + threadIdx.x;   // k*128 + n
    if (idx >= K_DIM * HD) return;
    int k = idx >> 7, n = idx & 127;
    float v = W[idx];
    __half hi = __float2half_rn(v);
    __half lo = __float2half_rn(v - __half2float(hi));
    g_Bhi[k * BPAD + n] = hi;
    g_Blo[k * BPAD + n] = lo;
}

// feat = x @ W via HMMA fp16 (A unsplit, W hi/lo split, fp32 accum).
// Epilogue: fp16 feat via smem + fused el/er.
__global__ void __launch_bounds__(256, 1)
gemm_mma(const float* __restrict__ x,
         const float* __restrict__ attn_l, const float* __restrict__ attn_r) {
    extern __shared__ char smem[];
    const uint32_t sb = smem_u32(smem);
    const int tid  = threadIdx.x;
    const int wid  = tid >> 5;
    const int lane = tid & 31;
    const int wm   = wid >> 1;          // m-group: rows wm*32..+31
    const int wn   = wid & 1;           // n-group: cols wn*64..+63
    const int lr   = lane & 15;
    const int lc   = lane >> 4;
    const int brow = blockIdx.x * 128;

    if (tid < 128) {
        ((float*)(smem + SM_ATTNL))[tid] = attn_l[tid];
        ((float*)(smem + SM_ATTNR))[tid] = attn_r[tid];
    }
    // stage W (padded, pre-split fp16): 2 x 69632 B linear copy
    {
        const uint4* bh = (const uint4*)g_Bhi;
        const uint4* bl = (const uint4*)g_Blo;
        uint4* dh = (uint4*)(smem + BS_HI);
        uint4* dl = (uint4*)(smem + BS_LO);
        #pragma unroll
        for (int i = 0; i < 17; i++) {          // 4352 uint4 each
            dh[i * 256 + tid] = bh[i * 256 + tid];
            dl[i * 256 + tid] = bl[i * 256 + tid];
        }
    }

    float acc[2][8][4];
    #pragma unroll
    for (int f = 0; f < 2; f++)
        #pragma unroll
        for (int t = 0; t < 8; t++)
            #pragma unroll
            for (int i = 0; i < 4; i++) acc[f][t][i] = 0.f;

    const float4* x4 = (const float4*)x;

    #pragma unroll
    for (int phase = 0; phase < 2; phase++) {
        // stage A tile: 128 rows x 128 k, fp32 -> fp16 (packed cvt)
        #pragma unroll
        for (int i = 0; i < 8; i++) {
            int cid = i * 256 + tid;        // 2048 chunks of 8 k-elems
            int row = cid >> 4;
            int kc  = cid & 15;
            int gr  = brow + row;
            float4 v0 = make_float4(0.f, 0.f, 0.f, 0.f), v1 = v0;
            if (gr < N_NODES) {
                v0 = x4[(size_t)gr * 64 + phase * 32 + kc * 2];
                v1 = x4[(size_t)gr * 64 + phase * 32 + kc * 2 + 1];
            }
            __align__(16) __half2 h[4];
            h[0] = __floats2half2_rn(v0.x, v0.y);
            h[1] = __floats2half2_rn(v0.z, v0.w);
            h[2] = __floats2half2_rn(v1.x, v1.y);
            h[3] = __floats2half2_rn(v1.z, v1.w);
            *(uint4*)(smem + AS_OFF + row * (BPAD * 2) + kc * 16) = *(const uint4*)h;
        }
        __syncthreads();

        #pragma unroll
        for (int step = 0; step < 8; step++) {
            const int k0 = step * 16;
            uint32_t ah[2][4];
            uint32_t aBase = sb + AS_OFF +
                (uint32_t)((wm * 32 + lr) * (BPAD * 2) + lc * 16 + k0 * 2);
            ldsm4(ah[0], aBase);
            ldsm4(ah[1], aBase + 16 * (BPAD * 2));
            #pragma unroll
            for (int j = 0; j < 4; j++) {
                uint32_t bAddr = sb + BS_HI +
                    (uint32_t)((phase * 128 + k0 + lr) * (BPAD * 2) +
                               (wn * 64 + j * 16 + lc * 8) * 2);
                uint32_t bh[4], bl[4];
                ldsm4t(bh, bAddr);
                ldsm4t(bl, bAddr + (BS_LO - BS_HI));
                #pragma unroll
                for (int f = 0; f < 2; f++) {
                    mma_f16(acc[f][2 * j],     ah[f], bh[0], bh[1]);
                    mma_f16(acc[f][2 * j],     ah[f], bl[0], bl[1]);
                    mma_f16(acc[f][2 * j + 1], ah[f], bh[2], bh[3]);
                    mma_f16(acc[f][2 * j + 1], ah[f], bl[2], bl[3]);
                }
            }
        }
        __syncthreads();   // A tile reusable next phase / feat tile after loop
    }

    // epilogue: acc -> fp16 tile in smem (reuse A area, padded stride)
    #pragma unroll
    for (int f = 0; f < 2; f++) {
        #pragma unroll
        for (int t = 0; t < 8; t++) {
            int row0 = wm * 32 + f * 16 + (lane >> 2);
            int colB = (wn * 64 + t * 8 + (lane & 3) * 2) * 2;
            *(__half2*)(smem + row0 * (BPAD * 2) + colB) =
                __floats2half2_rn(acc[f][t][0], acc[f][t][1]);
            *(__half2*)(smem + (row0 + 8) * (BPAD * 2) + colB) =
                __floats2half2_rn(acc[f][t][2], acc[f][t][3]);
        }
    }
    __syncthreads();

    // coalesced fp16 feat write
    #pragma unroll
    for (int i = 0; i < 8; i++) {
        int q   = i * 256 + tid;            // 2048 x 16B chunks
        int row = q >> 4;
        int cq  = q & 15;
        int gr  = brow + row;
        if (gr < N_NODES)
            ((uint4*)g_feat_h)[(size_t)gr * 16 + cq] =
                *(const uint4*)(smem + row * (BPAD * 2) + cq * 16);
    }

    // fused el/er from the smem fp16 tile
    if (tid < 128) {
        int gr = brow + tid;
        if (gr < N_NODES) {
            const float* sl = (const float*)(smem + SM_ATTNL);
            const float* sr = (const float*)(smem + SM_ATTNR);
            float el[4] = {0.f, 0.f, 0.f, 0.f}, er[4] = {0.f, 0.f, 0.f, 0.f};
            #pragma unroll
            for (int c16 = 0; c16 < 16; c16++) {
                uint4 raw = *(const uint4*)(smem + tid * (BPAD * 2) + c16 * 16);
                const __half2* hp = (const __half2*)&raw;
                int h = c16 >> 2;
                #pragma unroll
                for (int j = 0; j < 4; j++) {
                    float2 fv = __half22float2(hp[j]);
                    int col = c16 * 8 + j * 2;
                    el[h] += fv.x * sl[col] + fv.y * sl[col + 1];
                    er[h] += fv.x * sr[col] + fv.y * sr[col + 1];
                }
            }
            #pragma unroll
            for (int h = 0; h < 4; h++) {
                g_el[gr * 4 + h] = el[h];
                g_er[gr * 4 + h] = er[h];
            }
        }
    }
}

// fused: ex = exp(lrelu(el[src]+er[dst])); store; denom[dst] += ex.
// (softmax is shift-invariant; logits bounded, so no segment_max needed)
__global__ void edge_kernel(const int* __restrict__ src,
                            const int* __restrict__ dst) {
    int e = blockIdx.x * blockDim.x + threadIdx.x;
    if (e >= N_EDGES) return;
    int s = src[e], d = dst[e];
    float4 l = __ldg((const float4*)g_el + s);
    float4 r = __ldg((const float4*)g_er + d);
    float4 ex;
    ex.x = __expf(lrelu(l.x + r.x));
    ex.y = __expf(lrelu(l.y + r.y));
    ex.z = __expf(lrelu(l.z + r.z));
    ex.w = __expf(lrelu(l.w + r.w));
    ((float4*)g_e)[e] = ex;
    atomicAdd((float4*)(g_denom + d * 4), ex);
}

__global__ void node_inv_kernel() {
    int i = blockIdx.x * blockDim.x + threadIdx.x;
    if (i >= N_NODES * HEADS) return;
    g_inv[i] = 0.25f / fmaxf(g_denom[i], 1e-9f);
}

// aggregation: 4 threads per edge; thread t owns out dims t*8..t*8+7.
__global__ void aggregate_kernel(const int* __restrict__ src,
                                 const int* __restrict__ dst,
                                 float* __restrict__ out) {
    unsigned gt = blockIdx.x * blockDim.x + threadIdx.x;
    int e = gt >> 2;
    int t = gt & 3;
    if (e >= N_EDGES) return;
    int s = __ldg(src + e);
    int d = __ldg(dst + e);
    float4 ex  = __ldg((const float4*)g_e + e);
    float4 inv = __ldg((const float4*)g_inv + d);
    float a[4] = {ex.x * inv.x, ex.y * inv.y, ex.z * inv.z, ex.w * inv.w};

    float acc[8] = {0.f, 0.f, 0.f, 0.f, 0.f, 0.f, 0.f, 0.f};
    const uint4* fh = (const uint4*)g_feat_h + (size_t)s * 16 + t;
    #pragma unroll
    for (int h = 0; h < 4; h++) {
        uint4 raw = __ldg(fh + h * 4);
        const __half2* hp = (const __half2*)&raw;
        #pragma unroll
        for (int j = 0; j < 4; j++) {
            float2 f = __half22float2(hp[j]);
            acc[2 * j]     += a[h] * f.x;
            acc[2 * j + 1] += a[h] * f.y;
        }
    }
    float4* op = (float4*)out + (size_t)d * 8 + t * 2;
    atomicAdd(op,     make_float4(acc[0], acc[1], acc[2], acc[3]));
    atomicAdd(op + 1, make_float4(acc[4], acc[5], acc[6], acc[7]));
}

// ---------------- launch ----------------------------------------------------
extern "C" void kernel_launch(void* const* d_in, const int* in_sizes, int n_in,
                              void* d_out, int out_size) {
    const float* x      = (const float*)d_in[0];
    const float* W      = (const float*)d_in[1];
    const float* attn_l = (const float*)d_in[2];
    const float* attn_r = (const float*)d_in[3];
    const int*   src    = (const int*)d_in[4];
    const int*   dst    = (const int*)d_in[5];
    float* out = (float*)d_out;

    cudaFuncSetAttribute(gemm_mma,
                         cudaFuncAttributeMaxDynamicSharedMemorySize, SM_TOTAL);

    init_kernel<<<(N_NODES * ODIM + 255) / 256, 256>>>(out);
    prep_W<<<(K_DIM * HD + 255) / 256, 256>>>(W);
    gemm_mma<<<(N_NODES + 127) / 128, 256, SM_TOTAL>>>(x, attn_l, attn_r);
    edge_kernel<<<(N_EDGES + 255) / 256, 256>>>(src, dst);
    node_inv_kernel<<<(N_NODES * HEADS + 255) / 256, 256>>>();
    aggregate_kernel<<<(N_EDGES * 4 + 255) / 256, 256>>>(src, dst, out);
}